// round 13
// baseline (speedup 1.0000x reference)
#include <cuda_runtime.h>
#include <math.h>

#define NQ       10
#define DIM      1024
#define NLAYERS  5
#define NTHREADS 512
#define NU       ((NLAYERS + 1) * NQ)      // 60 variational gates
#define NUF      (NU * 8)                  // 480 floats of gate matrices

// Precomputed variational gate matrices U = Rz(c)·Ry(b)·Rx(a), 8 floats each:
// u00r,u00i,u01r,u01i,u10r,u10i,u11r,u11i
__device__ float g_U[NUF];

// ---------------------------------------------------------------------------
// Prep kernel: build the 60 fused single-qubit matrices from theta.
// theta layout: [L+1][NQ][3] = (a=Rx, b=Ry, c=Rz) angles.
// ---------------------------------------------------------------------------
__global__ void pqc_prep_kernel(const float* __restrict__ theta) {
    int i = blockIdx.x * blockDim.x + threadIdx.x;
    if (i >= NU) return;
    float a = theta[i * 3 + 0];
    float b = theta[i * 3 + 1];
    float c = theta[i * 3 + 2];
    float ca = cosf(0.5f * a), sa = sinf(0.5f * a);
    float cb = cosf(0.5f * b), sb = sinf(0.5f * b);
    float cc = cosf(0.5f * c), sc = sinf(0.5f * c);
    // M = Ry(b) * Rx(a)
    float m00r =  cb * ca, m00i =  sb * sa;
    float m01r = -sb * ca, m01i = -cb * sa;
    float m10r =  sb * ca, m10i = -cb * sa;
    float m11r =  cb * ca, m11i = -sb * sa;
    // U = Rz(c) * M : row0 *= exp(-ic/2) = (cc - i sc), row1 *= (cc + i sc)
    float* u = &g_U[i * 8];
    u[0] = m00r * cc + m00i * sc;  u[1] = m00i * cc - m00r * sc;
    u[2] = m01r * cc + m01i * sc;  u[3] = m01i * cc - m01r * sc;
    u[4] = m10r * cc - m10i * sc;  u[5] = m10i * cc + m10r * sc;
    u[6] = m11r * cc - m11i * sc;  u[7] = m11i * cc + m11r * sc;
}

// CZ-ring diagonal sign for basis index k (wire q <-> bit 9-q; ring on wires
// maps to the ring of adjacent index bits incl. the (0,9) wrap pair).
__device__ __forceinline__ float cz_sign(int k) {
    int adj  = k & (k >> 1);               // adjacent-bit AND, bits 0..8
    int wrap = (k & (k >> 9)) & 1;         // bit0 & bit9
    return ((__popc(adj) + wrap) & 1) ? -1.0f : 1.0f;
}

// ---------------------------------------------------------------------------
// Main kernel: one CTA per batch element, state vector in shared memory.
// ---------------------------------------------------------------------------
__global__ void __launch_bounds__(NTHREADS)
pqc_main_kernel(const float* __restrict__ x,
                const float* __restrict__ lam,
                const float* __restrict__ w,
                float* __restrict__ out) {
    __shared__ float2 st[DIM];
    __shared__ float  sU[NUF];
    __shared__ float  sred[NTHREADS / 32];

    const int t = threadIdx.x;
    const int b = blockIdx.x;

    if (t < NUF) sU[t] = g_U[t];
    st[t]       = make_float2(t == 0 ? 1.0f : 0.0f, 0.0f);
    st[t + 512] = make_float2(0.0f, 0.0f);

    // Per-batch inputs (broadcast loads, L1-served)
    float xv[NQ];
#pragma unroll
    for (int q = 0; q < NQ; ++q) xv[q] = x[b * NQ + q];

    __syncthreads();

#pragma unroll 1
    for (int l = 0; l < NLAYERS; ++l) {
        // ---- variational layer l: 10 fused U gates, CZ ring fused into q=9
#pragma unroll
        for (int q = 0; q < NQ; ++q) {
            const int p  = NQ - 1 - q;                     // target bit
            const float* u = &sU[(l * NQ + q) * 8];
            const int i0 = ((t >> p) << (p + 1)) | (t & ((1 << p) - 1));
            const int i1 = i0 | (1 << p);
            float2 a0 = st[i0], a1 = st[i1];
            float u0r = u[0], u0i = u[1], u1r = u[2], u1i = u[3];
            float u2r = u[4], u2i = u[5], u3r = u[6], u3i = u[7];
            float2 n0, n1;
            n0.x = u0r * a0.x - u0i * a0.y + u1r * a1.x - u1i * a1.y;
            n0.y = u0r * a0.y + u0i * a0.x + u1r * a1.y + u1i * a1.x;
            n1.x = u2r * a0.x - u2i * a0.y + u3r * a1.x - u3i * a1.y;
            n1.y = u2r * a0.y + u2i * a0.x + u3r * a1.y + u3i * a1.x;
            if (q == NQ - 1) {                             // fuse CZ diagonal
                float s0 = cz_sign(i0), s1 = cz_sign(i1);
                n0.x *= s0; n0.y *= s0;
                n1.x *= s1; n1.y *= s1;
            }
            st[i0] = n0; st[i1] = n1;
            __syncthreads();
        }
        // ---- encoding layer: Rx(x[b,q]*lam[l,q]) on each wire
#pragma unroll
        for (int q = 0; q < NQ; ++q) {
            const int p = NQ - 1 - q;
            float cg, sg;
            sincosf(0.5f * xv[q] * lam[l * NQ + q], &sg, &cg);
            const int i0 = ((t >> p) << (p + 1)) | (t & ((1 << p) - 1));
            const int i1 = i0 | (1 << p);
            float2 a0 = st[i0], a1 = st[i1];
            // Rx = [[c, -i s], [-i s, c]]
            float2 n0, n1;
            n0.x = cg * a0.x + sg * a1.y;
            n0.y = cg * a0.y - sg * a1.x;
            n1.x = cg * a1.x + sg * a0.y;
            n1.y = cg * a1.y - sg * a0.x;
            st[i0] = n0; st[i1] = n1;
            __syncthreads();
        }
    }

    // ---- final variational layer (trailing CZ ring skipped: pure phase,
    //      invariant under |amp|^2 for the diagonal Z^{⊗n} observable)
#pragma unroll
    for (int q = 0; q < NQ; ++q) {
        const int p  = NQ - 1 - q;
        const float* u = &sU[(NLAYERS * NQ + q) * 8];
        const int i0 = ((t >> p) << (p + 1)) | (t & ((1 << p) - 1));
        const int i1 = i0 | (1 << p);
        float2 a0 = st[i0], a1 = st[i1];
        float u0r = u[0], u0i = u[1], u1r = u[2], u1i = u[3];
        float u2r = u[4], u2i = u[5], u3r = u[6], u3i = u[7];
        float2 n0, n1;
        n0.x = u0r * a0.x - u0i * a0.y + u1r * a1.x - u1i * a1.y;
        n0.y = u0r * a0.y + u0i * a0.x + u1r * a1.y + u1i * a1.x;
        n1.x = u2r * a0.x - u2i * a0.y + u3r * a1.x - u3i * a1.y;
        n1.y = u2r * a0.y + u2i * a0.x + u3r * a1.y + u3i * a1.x;
        st[i0] = n0; st[i1] = n1;
        __syncthreads();
    }

    // ---- <Z^{⊗10}> : sign(k) = (-1)^popc(k); index t+512 flips sign of t
    float2 aL = st[t], aH = st[t + 512];
    float zs = (__popc(t) & 1) ? -1.0f : 1.0f;
    float partial = zs * ((aL.x * aL.x + aL.y * aL.y)
                        - (aH.x * aH.x + aH.y * aH.y));
#pragma unroll
    for (int off = 16; off; off >>= 1)
        partial += __shfl_down_sync(0xffffffffu, partial, off);
    if ((t & 31) == 0) sred[t >> 5] = partial;
    __syncthreads();

    if (t == 0) {
        float e = 0.0f;
#pragma unroll
        for (int i = 0; i < NTHREADS / 32; ++i) e += sred[i];
        // logits = e * w * beta (beta = 1), softmax over 2 actions
        float l0 = e * w[0], l1 = e * w[1];
        float m  = fmaxf(l0, l1);
        float e0 = expf(l0 - m), e1 = expf(l1 - m);
        float inv = 1.0f / (e0 + e1);
        out[2 * b + 0] = e0 * inv;
        out[2 * b + 1] = e1 * inv;
    }
}

// ---------------------------------------------------------------------------
// Launch. Inputs per metadata order: x [2048*10], theta [180], lam [50], w [2].
// Output: float32 [2048*2] softmax probabilities.
// ---------------------------------------------------------------------------
extern "C" void kernel_launch(void* const* d_in, const int* in_sizes, int n_in,
                              void* d_out, int out_size) {
    const float* x     = (const float*)d_in[0];
    const float* theta = (const float*)d_in[1];
    const float* lam   = (const float*)d_in[2];
    const float* w     = (const float*)d_in[3];
    float* out = (float*)d_out;

    const int B = in_sizes[0] / NQ;   // 2048

    pqc_prep_kernel<<<1, 64>>>(theta);
    pqc_main_kernel<<<B, NTHREADS>>>(x, lam, w, out);
}

// round 14
// speedup vs baseline: 3.0892x; 3.0892x over previous
#include <cuda_runtime.h>
#include <math.h>

#define NQ       10
#define DIM      1024
#define NLAYERS  5
#define NU       ((NLAYERS + 1) * NQ)   // 60 variational gates
#define NUF      (NU * 8)               // 480 floats of gate matrices
#define NLAM     (NLAYERS * NQ)         // 50
#define WARPS    8
#define THREADS  (WARPS * 32)

// Precomputed variational gate matrices U = Rz(c)*Ry(b)*Rx(a), 8 floats each:
// u00r,u00i,u01r,u01i,u10r,u10i,u11r,u11i
__device__ float g_U[NUF];

// ---------------------------------------------------------------------------
// Prep kernel: build the 60 fused single-qubit matrices from theta.
// ---------------------------------------------------------------------------
__global__ void pqc_prep_kernel(const float* __restrict__ theta) {
    int i = blockIdx.x * blockDim.x + threadIdx.x;
    if (i >= NU) return;
    float a = theta[i * 3 + 0];
    float b = theta[i * 3 + 1];
    float c = theta[i * 3 + 2];
    float ca = cosf(0.5f * a), sa = sinf(0.5f * a);
    float cb = cosf(0.5f * b), sb = sinf(0.5f * b);
    float cc = cosf(0.5f * c), sc = sinf(0.5f * c);
    // M = Ry(b) * Rx(a)
    float m00r =  cb * ca, m00i =  sb * sa;
    float m01r = -sb * ca, m01i = -cb * sa;
    float m10r =  sb * ca, m10i = -cb * sa;
    float m11r =  cb * ca, m11i = -sb * sa;
    // U = Rz(c) * M : row0 *= (cc - i sc), row1 *= (cc + i sc)
    float* u = &g_U[i * 8];
    u[0] = m00r * cc + m00i * sc;  u[1] = m00i * cc - m00r * sc;
    u[2] = m01r * cc + m01i * sc;  u[3] = m01i * cc - m01r * sc;
    u[4] = m10r * cc - m10i * sc;  u[5] = m10i * cc + m10r * sc;
    u[6] = m11r * cc - m11i * sc;  u[7] = m11i * cc + m11r * sc;
}

// ---------------------------------------------------------------------------
// Gate on a register bit P (wires 5..9 map to index bits 4..0).
// Fully unrolled: all c[] indices are compile-time constants.
// ---------------------------------------------------------------------------
template<int P>
__device__ __forceinline__ void gate_reg(float* cr, float* ci, const float* g) {
    const float g0 = g[0], g1 = g[1], g2 = g[2], g3 = g[3];
    const float g4 = g[4], g5 = g[5], g6 = g[6], g7 = g[7];
#pragma unroll
    for (int base = 0; base < 32; ++base) {
        if (base & (1 << P)) continue;
        const int i0 = base, i1 = base | (1 << P);
        float a0r = cr[i0], a0i = ci[i0];
        float a1r = cr[i1], a1i = ci[i1];
        cr[i0] = g0 * a0r - g1 * a0i + g2 * a1r - g3 * a1i;
        ci[i0] = g0 * a0i + g1 * a0r + g2 * a1i + g3 * a1r;
        cr[i1] = g4 * a0r - g5 * a0i + g6 * a1r - g7 * a1i;
        ci[i1] = g4 * a0i + g5 * a0r + g6 * a1i + g7 * a1r;
    }
}

// ---------------------------------------------------------------------------
// Gate on a lane bit M (wires 0..4 map to lane bits 4..0).
// Partner amplitudes come via shfl.xor; lane with target-bit==0 computes the
// "row 0" output, lane with target-bit==1 the "row 1" output.
// ---------------------------------------------------------------------------
template<int M>
__device__ __forceinline__ void gate_lane(float* cr, float* ci, const float* g, int lane) {
    const bool hi = (lane >> M) & 1;
    const float Ar = hi ? g[6] : g[0];
    const float Ai = hi ? g[7] : g[1];
    const float Br = hi ? g[4] : g[2];
    const float Bi = hi ? g[5] : g[3];
#pragma unroll
    for (int r = 0; r < 32; ++r) {
        float pr = __shfl_xor_sync(0xffffffffu, cr[r], 1 << M);
        float pi = __shfl_xor_sync(0xffffffffu, ci[r], 1 << M);
        float nr = Ar * cr[r] - Ai * ci[r] + Br * pr - Bi * pi;
        float ni = Ar * ci[r] + Ai * cr[r] + Br * pi + Bi * pr;
        cr[r] = nr; ci[r] = ni;
    }
}

// Build fused gate G = U(l,q) @ Rx(ang) for layers l>=1 (encoding fused in).
__device__ __forceinline__ void build_g(float* g, const float* __restrict__ sU,
                                        int l, int q, float ang_half) {
    const float* u = &sU[(l * NQ + q) * 8];
    float sg, cg;
    sincosf(ang_half, &sg, &cg);
    // Rx = [[cg, -i sg], [-i sg, cg]] applied FIRST:  G = U * Rx
    g[0] = cg * u[0] + sg * u[3];  g[1] = cg * u[1] - sg * u[2];
    g[2] = cg * u[2] + sg * u[1];  g[3] = cg * u[3] - sg * u[0];
    g[4] = cg * u[4] + sg * u[7];  g[5] = cg * u[5] - sg * u[6];
    g[6] = cg * u[6] + sg * u[5];  g[7] = cg * u[7] - sg * u[4];
}

// ---------------------------------------------------------------------------
// Main kernel: one WARP per batch element; state in registers (32 cplx/lane).
// Index k = (lane << 5) | r.  Wire q <-> index bit p = 9 - q.
// ---------------------------------------------------------------------------
__global__ void __launch_bounds__(THREADS)
pqc_warp_kernel(const float* __restrict__ x,
                const float* __restrict__ lam,
                const float* __restrict__ w,
                float* __restrict__ out,
                int B) {
    __shared__ float sU[NUF];
    __shared__ float sLam[NLAM];

    const int tid  = threadIdx.x;
    const int lane = tid & 31;
    const int b    = blockIdx.x * WARPS + (tid >> 5);

    for (int i = tid; i < NUF; i += THREADS) sU[i] = g_U[i];
    if (tid < NLAM) sLam[tid] = lam[tid];
    __syncthreads();
    if (b >= B) return;

    // --- CZ-ring diagonal sign mask for this lane's 32 register slots -----
    unsigned czmask = 0;
    for (int r = 0; r < 32; ++r) {
        int k   = (lane << 5) | r;
        int adj = k & (k >> 1);                          // adjacent-bit ring
        int par = (__popc(adj) + ((k >> 9) & k & 1)) & 1; // + (bit9 & bit0)
        czmask |= (unsigned)par << r;
    }

    // --- Layer 0 from |0...0>: state is a tensor product; build directly --
    float cr[32], ci[32];
    {
        // lane-bit wires (bit m <-> wire 4-m), column 0 of U(0, wire)
        float pr = 1.0f, pi = 0.0f;
#pragma unroll
        for (int m = 0; m < 5; ++m) {
            const float* u = &sU[(4 - m) * 8];
            int bit = (lane >> m) & 1;
            float ur = u[bit * 4 + 0], ui = u[bit * 4 + 1];
            float nr = pr * ur - pi * ui;
            float ni = pr * ui + pi * ur;
            pr = nr; pi = ni;
        }
        cr[0] = pr; ci[0] = pi;
        // register-bit wires (bit p <-> wire 9-p): doubling construction
#pragma unroll
        for (int p = 0; p < 5; ++p) {
            const float* u = &sU[(9 - p) * 8];
            float u0r = u[0], u0i = u[1], u1r = u[4], u1i = u[5];
#pragma unroll
            for (int r = 0; r < (1 << p); ++r) {
                float ar = cr[r], ai = ci[r];
                cr[r | (1 << p)] = ar * u1r - ai * u1i;
                ci[r | (1 << p)] = ar * u1i + ai * u1r;
                cr[r] = ar * u0r - ai * u0i;
                ci[r] = ar * u0i + ai * u0r;
            }
        }
    }

    // CZ after layer 0
#pragma unroll
    for (int r = 0; r < 32; ++r) {
        unsigned s = ((czmask >> r) & 1u) << 31;
        cr[r] = __uint_as_float(__float_as_uint(cr[r]) ^ s);
        ci[r] = __uint_as_float(__float_as_uint(ci[r]) ^ s);
    }

    // --- Layers 1..5: fused gates G = U(l,q) @ Rx(x_q * lam[l-1,q]) -------
    const float* xb = &x[b * NQ];
#pragma unroll 1
    for (int l = 1; l <= NLAYERS; ++l) {
        const float* lm = &sLam[(l - 1) * NQ];
        float g[8];
        // wires 0..4 -> lane bits 4..0
        build_g(g, sU, l, 0, 0.5f * xb[0] * lm[0]); gate_lane<4>(cr, ci, g, lane);
        build_g(g, sU, l, 1, 0.5f * xb[1] * lm[1]); gate_lane<3>(cr, ci, g, lane);
        build_g(g, sU, l, 2, 0.5f * xb[2] * lm[2]); gate_lane<2>(cr, ci, g, lane);
        build_g(g, sU, l, 3, 0.5f * xb[3] * lm[3]); gate_lane<1>(cr, ci, g, lane);
        build_g(g, sU, l, 4, 0.5f * xb[4] * lm[4]); gate_lane<0>(cr, ci, g, lane);
        // wires 5..9 -> register bits 4..0
        build_g(g, sU, l, 5, 0.5f * xb[5] * lm[5]); gate_reg<4>(cr, ci, g);
        build_g(g, sU, l, 6, 0.5f * xb[6] * lm[6]); gate_reg<3>(cr, ci, g);
        build_g(g, sU, l, 7, 0.5f * xb[7] * lm[7]); gate_reg<2>(cr, ci, g);
        build_g(g, sU, l, 8, 0.5f * xb[8] * lm[8]); gate_reg<1>(cr, ci, g);
        build_g(g, sU, l, 9, 0.5f * xb[9] * lm[9]); gate_reg<0>(cr, ci, g);
        if (l < NLAYERS) {   // CZ ring (final ring skipped: phase-only)
#pragma unroll
            for (int r = 0; r < 32; ++r) {
                unsigned s = ((czmask >> r) & 1u) << 31;
                cr[r] = __uint_as_float(__float_as_uint(cr[r]) ^ s);
                ci[r] = __uint_as_float(__float_as_uint(ci[r]) ^ s);
            }
        }
    }

    // --- <Z^{(x)10}> : sign = (-1)^popc(k) --------------------------------
    float sp = 0.0f, sn = 0.0f;
#pragma unroll
    for (int r = 0; r < 32; ++r) {
        float m2 = cr[r] * cr[r] + ci[r] * ci[r];
        if (__popc(r) & 1) sn += m2; else sp += m2;
    }
    float e = sp - sn;
    if (__popc(lane) & 1) e = -e;
#pragma unroll
    for (int off = 16; off; off >>= 1)
        e += __shfl_xor_sync(0xffffffffu, e, off);

    if (lane == 0) {
        float l0 = e * w[0], l1 = e * w[1];
        float m  = fmaxf(l0, l1);
        float e0 = expf(l0 - m), e1 = expf(l1 - m);
        float inv = 1.0f / (e0 + e1);
        out[2 * b + 0] = e0 * inv;
        out[2 * b + 1] = e1 * inv;
    }
}

// ---------------------------------------------------------------------------
extern "C" void kernel_launch(void* const* d_in, const int* in_sizes, int n_in,
                              void* d_out, int out_size) {
    const float* x     = (const float*)d_in[0];
    const float* theta = (const float*)d_in[1];
    const float* lam   = (const float*)d_in[2];
    const float* w     = (const float*)d_in[3];
    float* out = (float*)d_out;

    const int B = in_sizes[0] / NQ;   // 2048

    pqc_prep_kernel<<<1, 64>>>(theta);
    pqc_warp_kernel<<<(B + WARPS - 1) / WARPS, THREADS>>>(x, lam, w, out, B);
}